// round 14
// baseline (speedup 1.0000x reference)
#include <cuda_runtime.h>
#include <cuda_bf16.h>
#include <cstdint>

#define N_NODES 100000
#define N_EDGES 1600000
#define IN_F    128
#define OUT_F   128

#define GEMM_BLOCKS 782          // ceil(100000 / 128)
#define AGG_BLOCKS  12500        // 100000 nodes / 8 warps
#define RATIO       17           // 1 gemm block per 17 total (782*17 = 13294 >= 13282)
#define FUSED_BLOCKS (GEMM_BLOCKS + AGG_BLOCKS)   // 13282

// ---------------- scratch (static device globals; no runtime allocation) ----
__device__ int   g_deg[N_NODES];
__device__ int   g_off[N_NODES + 1];
__device__ int   g_pos[N_NODES];
__device__ int   g_csr[N_EDGES];
__device__ int   g_bsum[128];
__device__ float g_aggn[(size_t)N_NODES * IN_F];   // norm * segment_sum(feat[src], dst)
__device__ float g_V[(size_t)N_NODES * OUT_F];     // feat @ Wv

// ---------------- packed f32x2 helpers (sm_103a FFMA2) ----------------------
__device__ __forceinline__ unsigned long long fma_f32x2(unsigned long long a,
                                                        unsigned long long b,
                                                        unsigned long long c) {
    unsigned long long d;
    asm("fma.rn.f32x2 %0, %1, %2, %3;" : "=l"(d) : "l"(a), "l"(b), "l"(c));
    return d;
}
__device__ __forceinline__ unsigned long long pack_dup(float x) {
    unsigned long long d;
    asm("mov.b64 %0, {%1, %1};" : "=l"(d) : "f"(x));
    return d;
}
__device__ __forceinline__ float2 unpack_f32x2(unsigned long long v) {
    float lo, hi;
    asm("mov.b64 {%0, %1}, %2;" : "=f"(lo), "=f"(hi) : "l"(v));
    return make_float2(lo, hi);
}

// ---------------- CSR build ------------------------------------------------
__global__ void zero_kernel() {
    int i = blockIdx.x * 256 + threadIdx.x;
    if (i < N_NODES) { g_deg[i] = 0; g_pos[i] = 0; }
}

__global__ void count_kernel(const int* __restrict__ dst) {
    int e = blockIdx.x * 256 + threadIdx.x;
    if (e < N_EDGES) atomicAdd(&g_deg[dst[e]], 1);
}

__global__ void scanA_kernel() {
    __shared__ int sh[256];
    int t = threadIdx.x;
    int base = blockIdx.x * 1024 + t * 4;
    int v[4];
#pragma unroll
    for (int j = 0; j < 4; j++)
        v[j] = (base + j < N_NODES) ? g_deg[base + j] : 0;
    int tsum = v[0] + v[1] + v[2] + v[3];
    sh[t] = tsum;
    __syncthreads();
#pragma unroll
    for (int off = 1; off < 256; off <<= 1) {
        int x = (t >= off) ? sh[t - off] : 0;
        __syncthreads();
        sh[t] += x;
        __syncthreads();
    }
    int run = sh[t] - tsum;
    if (t == 255) g_bsum[blockIdx.x] = sh[255];
#pragma unroll
    for (int j = 0; j < 4; j++) {
        if (base + j < N_NODES) g_off[base + j] = run;
        run += v[j];
    }
}

__global__ void scanB_kernel() {
    __shared__ int sh[128];
    int t = threadIdx.x;
    int v = (t < 98) ? g_bsum[t] : 0;
    sh[t] = v;
    __syncthreads();
#pragma unroll
    for (int off = 1; off < 128; off <<= 1) {
        int x = (t >= off) ? sh[t - off] : 0;
        __syncthreads();
        sh[t] += x;
        __syncthreads();
    }
    if (t < 98) g_bsum[t] = sh[t] - v;
}

__global__ void scanC_kernel() {
    int i = blockIdx.x * 256 + threadIdx.x;
    if (i < N_NODES) g_off[i] += g_bsum[i >> 10];
    if (i == 0) g_off[N_NODES] = N_EDGES;
}

__global__ void scatter_kernel(const int* __restrict__ src,
                               const int* __restrict__ dst) {
    int e = blockIdx.x * 256 + threadIdx.x;
    if (e < N_EDGES) {
        int d = dst[e];
        int p = g_off[d] + atomicAdd(&g_pos[d], 1);
        g_csr[p] = src[e];
    }
}

// ---------------- GEMM tile: C_tile = A[R:R+128, 0:128] @ B(128x128) --------
// As stored k-major [BK][BM+4]; a-frag = packed f32x2 row-pairs (broadcast
// LDS.128), b-frag = two conflict-free LDS.128 + dup. FFMA2 inner loop.
#define BM 128
#define BN 128
#define BK 32
#define AS_LD (BM + 4)

template <bool FINAL>
__device__ __forceinline__ void gemm_tile(const float* __restrict__ A,
                                          const float* __restrict__ B,
                                          int R,
                                          const float* __restrict__ bias,
                                          float* __restrict__ C) {
    __shared__ float As[BK][AS_LD];
    __shared__ float Bs[BK][BN];

    int t  = threadIdx.x;
    int tx = t & 15;
    int ty = t >> 4;

    unsigned long long acc2[4][8];
#pragma unroll
    for (int p = 0; p < 4; p++)
#pragma unroll
        for (int j = 0; j < 8; j++) acc2[p][j] = 0ULL;

    for (int kc = 0; kc < 4; kc++) {
        int ka = kc * BK;

        // load A tile (128 rows x 32 k) -> transpose into k-major As
#pragma unroll
        for (int pp = 0; pp < 4; pp++) {
            int L  = pp * 256 + t;
            int m  = L >> 3;
            int k4 = (L & 7) * 4;
            float4 v = make_float4(0.f, 0.f, 0.f, 0.f);
            int gr = R + m;
            if (gr < N_NODES)
                v = *(const float4*)(A + (size_t)gr * 128 + ka + k4);
            As[k4 + 0][m] = v.x;
            As[k4 + 1][m] = v.y;
            As[k4 + 2][m] = v.z;
            As[k4 + 3][m] = v.w;
        }
        // load B tile (32 x 128)
#pragma unroll
        for (int pp = 0; pp < 4; pp++) {
            int L  = pp * 256 + t;
            int kr = L >> 5;
            int nq = (L & 31) * 4;
            float4 v = *(const float4*)(B + (size_t)(ka + kr) * 128 + nq);
            *(float4*)&Bs[kr][nq] = v;
        }
        __syncthreads();

#pragma unroll 8
        for (int kk = 0; kk < BK; kk++) {
            ulonglong2 ap0 = *(const ulonglong2*)&As[kk][ty * 8];
            ulonglong2 ap1 = *(const ulonglong2*)&As[kk][ty * 8 + 4];
            float4 b0 = *(const float4*)&Bs[kk][tx * 4];
            float4 b1 = *(const float4*)&Bs[kk][64 + tx * 4];
            unsigned long long bd[8];
            bd[0] = pack_dup(b0.x); bd[1] = pack_dup(b0.y);
            bd[2] = pack_dup(b0.z); bd[3] = pack_dup(b0.w);
            bd[4] = pack_dup(b1.x); bd[5] = pack_dup(b1.y);
            bd[6] = pack_dup(b1.z); bd[7] = pack_dup(b1.w);
            unsigned long long ap[4] = {ap0.x, ap0.y, ap1.x, ap1.y};
#pragma unroll
            for (int p = 0; p < 4; p++)
#pragma unroll
                for (int j = 0; j < 8; j++)
                    acc2[p][j] = fma_f32x2(ap[p], bd[j], acc2[p][j]);
        }
        __syncthreads();
    }

    // epilogue
    float bs[8];
    if (FINAL) {
#pragma unroll
        for (int j = 0; j < 4; j++) bs[j] = bias[tx * 4 + j];
#pragma unroll
        for (int j = 0; j < 4; j++) bs[4 + j] = bias[64 + tx * 4 + j];
    }

#pragma unroll
    for (int p = 0; p < 4; p++) {
        float2 c[8];
#pragma unroll
        for (int j = 0; j < 8; j++) c[j] = unpack_f32x2(acc2[p][j]);

#pragma unroll
        for (int half = 0; half < 2; half++) {
            int gr = R + ty * 8 + 2 * p + half;
            if (gr < N_NODES) {
                float v[8];
#pragma unroll
                for (int j = 0; j < 8; j++) v[j] = half ? c[j].y : c[j].x;

                float4 o0, o1;
                if (FINAL) {
                    const float* vp = g_V + (size_t)gr * 128;
                    float4 q0 = *(const float4*)(vp + tx * 4);
                    float4 q1 = *(const float4*)(vp + 64 + tx * 4);
                    o0.x = fmaxf(v[0] + q0.x + bs[0], 0.f);
                    o0.y = fmaxf(v[1] + q0.y + bs[1], 0.f);
                    o0.z = fmaxf(v[2] + q0.z + bs[2], 0.f);
                    o0.w = fmaxf(v[3] + q0.w + bs[3], 0.f);
                    o1.x = fmaxf(v[4] + q1.x + bs[4], 0.f);
                    o1.y = fmaxf(v[5] + q1.y + bs[5], 0.f);
                    o1.z = fmaxf(v[6] + q1.z + bs[6], 0.f);
                    o1.w = fmaxf(v[7] + q1.w + bs[7], 0.f);
                } else {
                    o0 = make_float4(v[0], v[1], v[2], v[3]);
                    o1 = make_float4(v[4], v[5], v[6], v[7]);
                }
                float* op = C + (size_t)gr * 128;
                *(float4*)(op + tx * 4)      = o0;
                *(float4*)(op + 64 + tx * 4) = o1;
            }
        }
    }
}

// ---------------- aggregation body: one warp per node -----------------------
__device__ __forceinline__ void agg_node(const float4* __restrict__ feat4,
                                         int node) {
    int lane = threadIdx.x & 31;
    int s = g_off[node];
    int e = g_off[node + 1];

    float4 a0 = make_float4(0.f, 0.f, 0.f, 0.f);
    float4 a1 = make_float4(0.f, 0.f, 0.f, 0.f);
    float4 a2 = make_float4(0.f, 0.f, 0.f, 0.f);
    float4 a3 = make_float4(0.f, 0.f, 0.f, 0.f);

    int j = s;
    for (; j + 4 <= e; j += 4) {
        int s0 = g_csr[j], s1 = g_csr[j + 1], s2 = g_csr[j + 2], s3 = g_csr[j + 3];
        float4 v0 = feat4[s0 * 32 + lane];
        float4 v1 = feat4[s1 * 32 + lane];
        float4 v2 = feat4[s2 * 32 + lane];
        float4 v3 = feat4[s3 * 32 + lane];
        a0.x += v0.x; a0.y += v0.y; a0.z += v0.z; a0.w += v0.w;
        a1.x += v1.x; a1.y += v1.y; a1.z += v1.z; a1.w += v1.w;
        a2.x += v2.x; a2.y += v2.y; a2.z += v2.z; a2.w += v2.w;
        a3.x += v3.x; a3.y += v3.y; a3.z += v3.z; a3.w += v3.w;
    }
    for (; j < e; j++) {
        float4 v = feat4[g_csr[j] * 32 + lane];
        a0.x += v.x; a0.y += v.y; a0.z += v.z; a0.w += v.w;
    }
    a0.x += a1.x + a2.x + a3.x;
    a0.y += a1.y + a2.y + a3.y;
    a0.z += a1.z + a2.z + a3.z;
    a0.w += a1.w + a2.w + a3.w;

    int deg = e - s;
    float norm = (deg > 0) ? (1.0f / (float)deg) : 1.0f;
    a0.x *= norm; a0.y *= norm; a0.z *= norm; a0.w *= norm;

    ((float4*)g_aggn)[node * 32 + lane] = a0;
}

// ---------------- fused: agg (L2-bound) + V = feat@Wv (FMA-bound) -----------
// Role by blockIdx: every 17th block is a gemm tile so both kinds co-reside
// on each SM and use disjoint pipes.
__global__ void __launch_bounds__(256, 2)
fused_aggV_kernel(const float* __restrict__ feat,
                  const float* __restrict__ Wv) {
    int b = blockIdx.x;
    if (b % RATIO == 0) {
        int g = b / RATIO;               // 0 .. 781
        gemm_tile<false>(feat, Wv, g * BM, nullptr, g_V);
    } else {
        int a = b - b / RATIO - 1;       // 0 .. 12499
        int node = a * 8 + ((int)threadIdx.x >> 5);
        if (node < N_NODES)
            agg_node((const float4*)feat, node);
    }
}

// ---------------- tail: out = relu(V + aggn@Wu + bias) ----------------------
__global__ void __launch_bounds__(256, 2)
gemmU_kernel(const float* __restrict__ Wu,
             const float* __restrict__ bias,
             float* __restrict__ out) {
    gemm_tile<true>((const float*)g_aggn, Wu, blockIdx.x * BM, bias, out);
}

// ---------------- launch ----------------------------------------------------
extern "C" void kernel_launch(void* const* d_in, const int* in_sizes, int n_in,
                              void* d_out, int out_size) {
    const float* feat = (const float*)d_in[0];
    const float* wu   = (const float*)d_in[1];
    const float* wv   = (const float*)d_in[2];
    const float* bias = (const float*)d_in[3];
    const int*   src  = (const int*)d_in[4];
    const int*   dst  = (const int*)d_in[5];
    float*       out  = (float*)d_out;

    (void)in_sizes; (void)n_in; (void)out_size;

    zero_kernel     <<<391, 256>>>();
    count_kernel    <<<(N_EDGES + 255) / 256, 256>>>(dst);
    scanA_kernel    <<<98, 256>>>();
    scanB_kernel    <<<1, 128>>>();
    scanC_kernel    <<<391, 256>>>();
    scatter_kernel  <<<(N_EDGES + 255) / 256, 256>>>(src, dst);
    fused_aggV_kernel<<<FUSED_BLOCKS, 256>>>(feat, wv);
    gemmU_kernel    <<<GEMM_BLOCKS, 256>>>(wu, bias, out);
}

// round 15
// speedup vs baseline: 1.0018x; 1.0018x over previous
#include <cuda_runtime.h>
#include <cuda_bf16.h>
#include <cstdint>

#define N_NODES 100000
#define N_EDGES 1600000
#define IN_F    128
#define OUT_F   128

#define GEMM_BLOCKS 782          // ceil(100000 / 128)
#define AGG_BLOCKS  12500        // 100000 nodes / 8 warps
#define RATIO       17           // 1 gemm block per 17 total (782*17 = 13294 >= 13282)
#define FUSED_BLOCKS (GEMM_BLOCKS + AGG_BLOCKS)   // 13282

// ---------------- scratch (static device globals; no runtime allocation) ----
__device__ int   g_deg[N_NODES];
__device__ int   g_off[N_NODES + 1];
__device__ int   g_pos[N_NODES];
__device__ int   g_csr[N_EDGES];
__device__ int   g_bsum[128];
__device__ float g_aggn[(size_t)N_NODES * IN_F];   // norm * segment_sum(feat[src], dst)
__device__ float g_V[(size_t)N_NODES * OUT_F];     // feat @ Wv

// ---------------- packed f32x2 helpers (sm_103a FFMA2) ----------------------
__device__ __forceinline__ unsigned long long fma_f32x2(unsigned long long a,
                                                        unsigned long long b,
                                                        unsigned long long c) {
    unsigned long long d;
    asm("fma.rn.f32x2 %0, %1, %2, %3;" : "=l"(d) : "l"(a), "l"(b), "l"(c));
    return d;
}
__device__ __forceinline__ unsigned long long pack_dup(float x) {
    unsigned long long d;
    asm("mov.b64 %0, {%1, %1};" : "=l"(d) : "f"(x));
    return d;
}
__device__ __forceinline__ float2 unpack_f32x2(unsigned long long v) {
    float lo, hi;
    asm("mov.b64 {%0, %1}, %2;" : "=f"(lo), "=f"(hi) : "l"(v));
    return make_float2(lo, hi);
}

// ---------------- CSR build ------------------------------------------------
__global__ void zero_kernel() {
    int i = blockIdx.x * 256 + threadIdx.x;
    if (i < N_NODES) { g_deg[i] = 0; g_pos[i] = 0; }
}

__global__ void count_kernel(const int* __restrict__ dst) {
    int e = blockIdx.x * 256 + threadIdx.x;
    if (e < N_EDGES) atomicAdd(&g_deg[dst[e]], 1);
}

__global__ void scanA_kernel() {
    __shared__ int sh[256];
    int t = threadIdx.x;
    int base = blockIdx.x * 1024 + t * 4;
    int v[4];
#pragma unroll
    for (int j = 0; j < 4; j++)
        v[j] = (base + j < N_NODES) ? g_deg[base + j] : 0;
    int tsum = v[0] + v[1] + v[2] + v[3];
    sh[t] = tsum;
    __syncthreads();
#pragma unroll
    for (int off = 1; off < 256; off <<= 1) {
        int x = (t >= off) ? sh[t - off] : 0;
        __syncthreads();
        sh[t] += x;
        __syncthreads();
    }
    int run = sh[t] - tsum;
    if (t == 255) g_bsum[blockIdx.x] = sh[255];
#pragma unroll
    for (int j = 0; j < 4; j++) {
        if (base + j < N_NODES) g_off[base + j] = run;
        run += v[j];
    }
}

__global__ void scanB_kernel() {
    __shared__ int sh[128];
    int t = threadIdx.x;
    int v = (t < 98) ? g_bsum[t] : 0;
    sh[t] = v;
    __syncthreads();
#pragma unroll
    for (int off = 1; off < 128; off <<= 1) {
        int x = (t >= off) ? sh[t - off] : 0;
        __syncthreads();
        sh[t] += x;
        __syncthreads();
    }
    if (t < 98) g_bsum[t] = sh[t] - v;
}

__global__ void scanC_kernel() {
    int i = blockIdx.x * 256 + threadIdx.x;
    if (i < N_NODES) g_off[i] += g_bsum[i >> 10];
    if (i == 0) g_off[N_NODES] = N_EDGES;
}

__global__ void scatter_kernel(const int* __restrict__ src,
                               const int* __restrict__ dst) {
    int e = blockIdx.x * 256 + threadIdx.x;
    if (e < N_EDGES) {
        int d = dst[e];
        int p = g_off[d] + atomicAdd(&g_pos[d], 1);
        g_csr[p] = src[e];
    }
}

// ---------------- GEMM tile: C_tile = A[R:R+128, 0:128] @ B(128x128) --------
// As stored k-major [BK][BM+4]; a-frag = packed f32x2 row-pairs (broadcast
// LDS.128), b-frag = two conflict-free LDS.128 + dup. FFMA2 inner loop.
#define BM 128
#define BN 128
#define BK 32
#define AS_LD (BM + 4)

template <bool FINAL>
__device__ __forceinline__ void gemm_tile(const float* __restrict__ A,
                                          const float* __restrict__ B,
                                          int R,
                                          const float* __restrict__ bias,
                                          float* __restrict__ C) {
    __shared__ float As[BK][AS_LD];
    __shared__ float Bs[BK][BN];

    int t  = threadIdx.x;
    int tx = t & 15;
    int ty = t >> 4;

    unsigned long long acc2[4][8];
#pragma unroll
    for (int p = 0; p < 4; p++)
#pragma unroll
        for (int j = 0; j < 8; j++) acc2[p][j] = 0ULL;

    for (int kc = 0; kc < 4; kc++) {
        int ka = kc * BK;

        // load A tile (128 rows x 32 k) -> transpose into k-major As
#pragma unroll
        for (int pp = 0; pp < 4; pp++) {
            int L  = pp * 256 + t;
            int m  = L >> 3;
            int k4 = (L & 7) * 4;
            float4 v = make_float4(0.f, 0.f, 0.f, 0.f);
            int gr = R + m;
            if (gr < N_NODES)
                v = *(const float4*)(A + (size_t)gr * 128 + ka + k4);
            As[k4 + 0][m] = v.x;
            As[k4 + 1][m] = v.y;
            As[k4 + 2][m] = v.z;
            As[k4 + 3][m] = v.w;
        }
        // load B tile (32 x 128)
#pragma unroll
        for (int pp = 0; pp < 4; pp++) {
            int L  = pp * 256 + t;
            int kr = L >> 5;
            int nq = (L & 31) * 4;
            float4 v = *(const float4*)(B + (size_t)(ka + kr) * 128 + nq);
            *(float4*)&Bs[kr][nq] = v;
        }
        __syncthreads();

#pragma unroll 8
        for (int kk = 0; kk < BK; kk++) {
            ulonglong2 ap0 = *(const ulonglong2*)&As[kk][ty * 8];
            ulonglong2 ap1 = *(const ulonglong2*)&As[kk][ty * 8 + 4];
            float4 b0 = *(const float4*)&Bs[kk][tx * 4];
            float4 b1 = *(const float4*)&Bs[kk][64 + tx * 4];
            unsigned long long bd[8];
            bd[0] = pack_dup(b0.x); bd[1] = pack_dup(b0.y);
            bd[2] = pack_dup(b0.z); bd[3] = pack_dup(b0.w);
            bd[4] = pack_dup(b1.x); bd[5] = pack_dup(b1.y);
            bd[6] = pack_dup(b1.z); bd[7] = pack_dup(b1.w);
            unsigned long long ap[4] = {ap0.x, ap0.y, ap1.x, ap1.y};
#pragma unroll
            for (int p = 0; p < 4; p++)
#pragma unroll
                for (int j = 0; j < 8; j++)
                    acc2[p][j] = fma_f32x2(ap[p], bd[j], acc2[p][j]);
        }
        __syncthreads();
    }

    // epilogue
    float bs[8];
    if (FINAL) {
#pragma unroll
        for (int j = 0; j < 4; j++) bs[j] = bias[tx * 4 + j];
#pragma unroll
        for (int j = 0; j < 4; j++) bs[4 + j] = bias[64 + tx * 4 + j];
    }

#pragma unroll
    for (int p = 0; p < 4; p++) {
        float2 c[8];
#pragma unroll
        for (int j = 0; j < 8; j++) c[j] = unpack_f32x2(acc2[p][j]);

#pragma unroll
        for (int half = 0; half < 2; half++) {
            int gr = R + ty * 8 + 2 * p + half;
            if (gr < N_NODES) {
                float v[8];
#pragma unroll
                for (int j = 0; j < 8; j++) v[j] = half ? c[j].y : c[j].x;

                float4 o0, o1;
                if (FINAL) {
                    const float* vp = g_V + (size_t)gr * 128;
                    float4 q0 = *(const float4*)(vp + tx * 4);
                    float4 q1 = *(const float4*)(vp + 64 + tx * 4);
                    o0.x = fmaxf(v[0] + q0.x + bs[0], 0.f);
                    o0.y = fmaxf(v[1] + q0.y + bs[1], 0.f);
                    o0.z = fmaxf(v[2] + q0.z + bs[2], 0.f);
                    o0.w = fmaxf(v[3] + q0.w + bs[3], 0.f);
                    o1.x = fmaxf(v[4] + q1.x + bs[4], 0.f);
                    o1.y = fmaxf(v[5] + q1.y + bs[5], 0.f);
                    o1.z = fmaxf(v[6] + q1.z + bs[6], 0.f);
                    o1.w = fmaxf(v[7] + q1.w + bs[7], 0.f);
                } else {
                    o0 = make_float4(v[0], v[1], v[2], v[3]);
                    o1 = make_float4(v[4], v[5], v[6], v[7]);
                }
                float* op = C + (size_t)gr * 128;
                *(float4*)(op + tx * 4)      = o0;
                *(float4*)(op + 64 + tx * 4) = o1;
            }
        }
    }
}

// ---------------- aggregation body: one warp per node -----------------------
__device__ __forceinline__ void agg_node(const float4* __restrict__ feat4,
                                         int node) {
    int lane = threadIdx.x & 31;
    int s = g_off[node];
    int e = g_off[node + 1];

    float4 a0 = make_float4(0.f, 0.f, 0.f, 0.f);
    float4 a1 = make_float4(0.f, 0.f, 0.f, 0.f);
    float4 a2 = make_float4(0.f, 0.f, 0.f, 0.f);
    float4 a3 = make_float4(0.f, 0.f, 0.f, 0.f);

    int j = s;
    for (; j + 4 <= e; j += 4) {
        int s0 = g_csr[j], s1 = g_csr[j + 1], s2 = g_csr[j + 2], s3 = g_csr[j + 3];
        float4 v0 = feat4[s0 * 32 + lane];
        float4 v1 = feat4[s1 * 32 + lane];
        float4 v2 = feat4[s2 * 32 + lane];
        float4 v3 = feat4[s3 * 32 + lane];
        a0.x += v0.x; a0.y += v0.y; a0.z += v0.z; a0.w += v0.w;
        a1.x += v1.x; a1.y += v1.y; a1.z += v1.z; a1.w += v1.w;
        a2.x += v2.x; a2.y += v2.y; a2.z += v2.z; a2.w += v2.w;
        a3.x += v3.x; a3.y += v3.y; a3.z += v3.z; a3.w += v3.w;
    }
    for (; j < e; j++) {
        float4 v = feat4[g_csr[j] * 32 + lane];
        a0.x += v.x; a0.y += v.y; a0.z += v.z; a0.w += v.w;
    }
    a0.x += a1.x + a2.x + a3.x;
    a0.y += a1.y + a2.y + a3.y;
    a0.z += a1.z + a2.z + a3.z;
    a0.w += a1.w + a2.w + a3.w;

    int deg = e - s;
    float norm = (deg > 0) ? (1.0f / (float)deg) : 1.0f;
    a0.x *= norm; a0.y *= norm; a0.z *= norm; a0.w *= norm;

    ((float4*)g_aggn)[node * 32 + lane] = a0;
}

// ---------------- fused: agg (L2-bound) + V = feat@Wv (FMA-bound) -----------
// Role by blockIdx: every 17th block is a gemm tile so both kinds co-reside
// on each SM and use disjoint pipes.
__global__ void __launch_bounds__(256, 2)
fused_aggV_kernel(const float* __restrict__ feat,
                  const float* __restrict__ Wv) {
    int b = blockIdx.x;
    if (b % RATIO == 0) {
        int g = b / RATIO;               // 0 .. 781
        gemm_tile<false>(feat, Wv, g * BM, nullptr, g_V);
    } else {
        int a = b - b / RATIO - 1;       // 0 .. 12499
        int node = a * 8 + ((int)threadIdx.x >> 5);
        if (node < N_NODES)
            agg_node((const float4*)feat, node);
    }
}

// ---------------- tail: out = relu(V + aggn@Wu + bias) ----------------------
__global__ void __launch_bounds__(256, 2)
gemmU_kernel(const float* __restrict__ Wu,
             const float* __restrict__ bias,
             float* __restrict__ out) {
    gemm_tile<true>((const float*)g_aggn, Wu, blockIdx.x * BM, bias, out);
}

// ---------------- launch ----------------------------------------------------
extern "C" void kernel_launch(void* const* d_in, const int* in_sizes, int n_in,
                              void* d_out, int out_size) {
    const float* feat = (const float*)d_in[0];
    const float* wu   = (const float*)d_in[1];
    const float* wv   = (const float*)d_in[2];
    const float* bias = (const float*)d_in[3];
    const int*   src  = (const int*)d_in[4];
    const int*   dst  = (const int*)d_in[5];
    float*       out  = (float*)d_out;

    (void)in_sizes; (void)n_in; (void)out_size;

    zero_kernel     <<<391, 256>>>();
    count_kernel    <<<(N_EDGES + 255) / 256, 256>>>(dst);
    scanA_kernel    <<<98, 256>>>();
    scanB_kernel    <<<1, 128>>>();
    scanC_kernel    <<<391, 256>>>();
    scatter_kernel  <<<(N_EDGES + 255) / 256, 256>>>(src, dst);
    fused_aggV_kernel<<<FUSED_BLOCKS, 256>>>(feat, wv);
    gemmU_kernel    <<<GEMM_BLOCKS, 256>>>(wu, bias, out);
}